// round 11
// baseline (speedup 1.0000x reference)
#include <cuda_runtime.h>
#include <cuda_bf16.h>
#include <math.h>

#define BB 64
#define SS 64
#define HH 1024
#define TT 40
#define VV 32000

#define LOGITS_BLKS (VV / 128)          // 250
#define QGH2_BLKS   64                  // 32 n-tiles x 2 K-slices
#define SMEM_DYN    73728               // 3 x 24576 (3-stage cp.async pipeline)
#define NBLK2       128                 // attn_gi_gru grid (co-resident <= 148)

// ---------------- scratch (device globals; no allocation allowed) ----------
__device__ float g_keysU[BB * SS * HH];                  // 16.8 MB fp32
__device__ float g_h[BB * HH];
__device__ float g_logits[BB * VV];                      // 8.2 MB
__device__ float g_qghp[2][BB * 4 * HH];                 // qgh split-K partials
__device__ float g_gipart[4][BB * 3 * HH];
__device__ float g_scores[BB * SS];
__device__ int   g_b2[2];                                // [arrive, epoch]
__device__ __nv_bfloat16 g_wout16[(long)VV * HH];        // 65.5 MB
__device__ __nv_bfloat16 g_eo3[(long)BB * SS * 3 * HH];  // [hi,hi,lo] 25 MB
__device__ __nv_bfloat16 g_ua3[(long)HH * 3 * HH];       // [hi,lo,hi] 6 MB
__device__ __nv_bfloat16 g_wqh3[(long)4 * HH * 3 * HH];  // [Wa;Whh] x3, 25 MB
__device__ __nv_bfloat16 g_wih3[(long)3 * HH * 6 * HH];  // W_ih x3, 37.7 MB
__device__ __nv_bfloat16 g_h3[BB * 3 * HH];              // [hi | hi | lo]
__device__ __nv_bfloat16 g_x3[BB * 6 * HH];              // [xhi | xhi | xlo]

// ---------------------------------------------------------------------------
// helpers
// ---------------------------------------------------------------------------
__device__ __forceinline__ float fast_tanh(float x) {
    float y;
    asm("tanh.approx.f32 %0, %1;" : "=f"(y) : "f"(x));
    return y;
}
__device__ __forceinline__ unsigned sptr(const void* p) {
    return (unsigned)__cvta_generic_to_shared(p);
}
__device__ __forceinline__ void cpa16(unsigned dst, const void* src) {
    asm volatile("cp.async.cg.shared.global [%0], [%1], 16;" :: "r"(dst), "l"(src));
}
__device__ __forceinline__ void ldm4(unsigned* r, unsigned addr) {
    asm volatile("ldmatrix.sync.aligned.m8n8.x4.shared.b16 {%0,%1,%2,%3}, [%4];"
                 : "=r"(r[0]), "=r"(r[1]), "=r"(r[2]), "=r"(r[3]) : "r"(addr));
}
__device__ __forceinline__ void mma_bf16(float* d, const unsigned* a,
                                         unsigned b0, unsigned b1) {
    asm volatile(
        "mma.sync.aligned.m16n8k16.row.col.f32.bf16.bf16.f32 "
        "{%0,%1,%2,%3}, {%4,%5,%6,%7}, {%8,%9}, {%0,%1,%2,%3};"
        : "+f"(d[0]), "+f"(d[1]), "+f"(d[2]), "+f"(d[3])
        : "r"(a[0]), "r"(a[1]), "r"(a[2]), "r"(a[3]), "r"(b0), "r"(b1));
}

// grid-wide sense-reversal barrier for the 128-block attn_gi_gru kernel
__device__ __forceinline__ void gbar2()
{
    __syncthreads();
    if (threadIdx.x == 0) {
        __threadfence();
        int e = ((volatile int*)g_b2)[1];
        if (atomicAdd(&g_b2[0], 1) == NBLK2 - 1) {
            g_b2[0] = 0;
            __threadfence();
            ((volatile int*)g_b2)[1] = e + 1;
        } else {
            while (((volatile int*)g_b2)[1] == e) __nanosleep(32);
        }
        __threadfence();
    }
    __syncthreads();
}

// ---------------------------------------------------------------------------
// Shared GEMM body: C[64, n0:n0+128] (+ bias) = A[64 rows, K'] @ B^T
// cp.async TRIPLE-buffered (wait_group 2), xor-swizzled smem, m16n8k16, 8 warps.
// (unchanged from R8 — proven)
// ---------------------------------------------------------------------------
__device__ __forceinline__ void gemm_body(
    const __nv_bfloat16* __restrict__ A, const __nv_bfloat16* __restrict__ Bw,
    const float* __restrict__ bias, float* __restrict__ C,
    int kcBegin, int kcPer, int lda, int ldb, int ldc,
    int m0, int n0, unsigned sb0)
{
    const unsigned BUF = 24576u;
    const int tid = threadIdx.x;
    const int wid = tid >> 5, lane = tid & 31;
    const int warp_m = wid >> 2;
    const int warp_n = wid & 3;

    float acc[2][4][4];
#pragma unroll
    for (int a = 0; a < 2; a++)
#pragma unroll
        for (int b = 0; b < 4; b++)
#pragma unroll
            for (int c = 0; c < 4; c++) acc[a][b][c] = 0.f;

    auto stage = [&](unsigned sbase, int kc) {
#pragma unroll
        for (int i = 0; i < 6; i++) {
            int idx = tid + i * 256;
            if (idx < 512) {
                int r = idx >> 3, c = idx & 7;
                unsigned dst = sbase + (unsigned)(((r << 3) + (c ^ (r & 7))) << 4);
                cpa16(dst, A + (long)(m0 + r) * lda + kc * 64 + c * 8);
            } else {
                int j = idx - 512;
                int r = j >> 3, c = j & 7;
                unsigned dst = sbase + 8192u + (unsigned)(((r << 3) + (c ^ (r & 7))) << 4);
                cpa16(dst, Bw + (long)(n0 + r) * ldb + kc * 64 + c * 8);
            }
        }
    };

    stage(sb0, kcBegin);
    asm volatile("cp.async.commit_group;");
    if (kcPer > 1) stage(sb0 + BUF, kcBegin + 1);
    asm volatile("cp.async.commit_group;");

    for (int i = 0; i < kcPer; i++) {
        if (i + 2 < kcPer) stage(sb0 + (unsigned)((i + 2) % 3) * BUF, kcBegin + i + 2);
        asm volatile("cp.async.commit_group;");
        asm volatile("cp.async.wait_group 2;");
        __syncthreads();

        const unsigned bA = sb0 + (unsigned)(i % 3) * BUF;
        const unsigned bB = bA + 8192u;

#pragma unroll
        for (int kk = 0; kk < 4; kk++) {
            unsigned afr[2][4], bfr[2][4];
#pragma unroll
            for (int mt = 0; mt < 2; mt++) {
                int r = warp_m * 32 + mt * 16 + (lane & 15);
                int c = 2 * kk + (lane >> 4);
                ldm4(afr[mt], bA + (unsigned)(((r << 3) + (c ^ (r & 7))) << 4));
            }
#pragma unroll
            for (int np = 0; np < 2; np++) {
                int r = warp_n * 32 + np * 16 + ((lane >> 4) << 3) + (lane & 7);
                int c = 2 * kk + ((lane >> 3) & 1);
                ldm4(bfr[np], bB + (unsigned)(((r << 3) + (c ^ (r & 7))) << 4));
            }
#pragma unroll
            for (int mt = 0; mt < 2; mt++)
#pragma unroll
                for (int nt = 0; nt < 4; nt++)
                    mma_bf16(acc[mt][nt], afr[mt],
                             bfr[nt >> 1][(nt & 1) * 2], bfr[nt >> 1][(nt & 1) * 2 + 1]);
        }
        __syncthreads();
    }

    // drain remaining async groups so later phases can safely reuse smem
    asm volatile("cp.async.wait_group 0;");
    __syncthreads();

#pragma unroll
    for (int mt = 0; mt < 2; mt++) {
        int row = m0 + warp_m * 32 + mt * 16 + (lane >> 2);
#pragma unroll
        for (int nt = 0; nt < 4; nt++) {
            int col = n0 + warp_n * 32 + nt * 8 + ((lane & 3) << 1);
            float* cp = C + (long)row * ldc + col;
            float b0 = 0.f, b1 = 0.f;
            if (bias) { b0 = bias[col]; b1 = bias[col + 1]; }
            float2 v0 = {acc[mt][nt][0] + b0, acc[mt][nt][1] + b1};
            float2 v1 = {acc[mt][nt][2] + b0, acc[mt][nt][3] + b1};
            *(float2*)cp = v0;
            *(float2*)(cp + (long)8 * ldc) = v1;
        }
    }
}

// Generic wrapper (keysU one-time GEMM)
__global__ void gemm_mma(const __nv_bfloat16* __restrict__ A,
                         const __nv_bfloat16* __restrict__ Bw,
                         const float* __restrict__ bias,
                         float* __restrict__ C,
                         int kcPer, int lda, int ldb, int N, long strideZ)
{
    extern __shared__ unsigned char smem_raw[];
    gemm_body(A, Bw, bias, C + (long)blockIdx.z * strideZ,
              blockIdx.z * kcPer, kcPer, lda, ldb, N,
              blockIdx.y * 64, blockIdx.x * 128, sptr(smem_raw));
}

// ---------------------------------------------------------------------------
// MEGA GEMM: qgh split-K partials (blocks 0..63, mode&2) + logits (64.., mode&1)
// (unchanged from R8 — proven)
// ---------------------------------------------------------------------------
__global__ void mega_gemm(const float* __restrict__ b_out, int mode)
{
    extern __shared__ unsigned char smem_raw[];
    const int bx = blockIdx.x;
    if (bx < QGH2_BLKS) {
        if (!(mode & 2)) return;
        const int z = bx >> 5;          // K-slice 0/1
        const int n0 = (bx & 31) * 128;
        gemm_body(g_h3, g_wqh3, nullptr, g_qghp[z],
                  z * 24, 24, 3 * HH, 3 * HH, 4 * HH, 0, n0, sptr(smem_raw));
    } else {
        if (!(mode & 1)) return;
        gemm_body(g_h3, g_wout16, b_out, g_logits,
                  0, 16, 3 * HH, HH, VV, 0, (bx - QGH2_BLKS) * 128, sptr(smem_raw));
    }
}

// ---------------------------------------------------------------------------
// attn scores + softmax/ctx/x3 || lsm + gi + gru : ONE launch, 128 blocks.
// Static __shared__ for phase scratch (R8-proven); dynamic smem only in gemm.
// ---------------------------------------------------------------------------
__global__ void __launch_bounds__(256)
attn_gi_gru(const float* __restrict__ EO,
            const float* __restrict__ Va,
            const float* __restrict__ bv,
            const float* __restrict__ ba,
            const float* __restrict__ emb,
            const int* __restrict__ target,
            const float* __restrict__ b_ih,
            const float* __restrict__ b_hh,
            float* __restrict__ out_attn,
            float* __restrict__ out_dec,
            int t)
{
    extern __shared__ unsigned char smem_raw[];
    __shared__ float s_q[HH];
    __shared__ float s_v[HH];
    __shared__ float s_w[SS];
    __shared__ float s_red[256];
    const int bid = blockIdx.x;
    const int tid = threadIdx.x;
    const int warp = tid >> 5, lane = tid & 31;

    // ---- Phase A: attention scores, 2 blocks per batch row ----
    if (t < TT) {
        const int b = bid >> 1;
        const int s0 = (bid & 1) * 32;
        for (int i = tid; i < HH; i += 256) {
            s_q[i] = g_qghp[0][b * 4 * HH + i] + g_qghp[1][b * 4 * HH + i] + ba[i];
            s_v[i] = Va[i];
        }
        __syncthreads();
        for (int s = warp; s < 32; s += 8) {
            const float* kp = &g_keysU[((long)(b * SS + s0 + s)) * HH];
            float sum = 0.f;
            for (int h = lane; h < HH; h += 32)
                sum += fast_tanh(s_q[h] + kp[h]) * s_v[h];
#pragma unroll
            for (int o = 16; o; o >>= 1) sum += __shfl_xor_sync(~0u, sum, o);
            if (!lane) g_scores[b * SS + s0 + s] = sum + bv[0];
        }
        gbar2();
    }

    // ---- Phase B: softmax+ctx+x3 (blocks 0..63) || lsm(t-1) (64..127) ----
    if (bid < 64) {
        if (t < TT) {
            const int b = bid;
            if (tid < 32) {
                float v0 = g_scores[b * SS + tid], v1 = g_scores[b * SS + tid + 32];
                float mx = fmaxf(v0, v1);
#pragma unroll
                for (int o = 16; o; o >>= 1) mx = fmaxf(mx, __shfl_xor_sync(~0u, mx, o));
                float e0 = expf(v0 - mx), e1 = expf(v1 - mx);
                float sm = e0 + e1;
#pragma unroll
                for (int o = 16; o; o >>= 1) sm += __shfl_xor_sync(~0u, sm, o);
                float inv = 1.f / sm;
                s_w[tid] = e0 * inv;
                s_w[tid + 32] = e1 * inv;
                out_attn[((long)(b * TT + t)) * SS + tid] = e0 * inv;
                out_attn[((long)(b * TT + t)) * SS + tid + 32] = e1 * inv;
            }
            __syncthreads();

            const int tok = (t == 0) ? 0 : target[b * TT + t - 1];  // SOS_INDEX=0
            __nv_bfloat16* xr = &g_x3[b * 6 * HH];
            for (int h = tid; h < HH; h += 256) {
                float acc = 0.f;
                const float* ep = &EO[(long)b * SS * HH + h];
#pragma unroll 8
                for (int s = 0; s < SS; s++) acc += s_w[s] * ep[(long)s * HH];
                __nv_bfloat16 chi = __float2bfloat16(acc);
                __nv_bfloat16 clo = __float2bfloat16(acc - __bfloat162float(chi));
                xr[1024 + h] = chi;
                xr[2048 + 1024 + h] = chi;
                xr[4096 + 1024 + h] = clo;
                float e = emb[(long)tok * HH + h];
                __nv_bfloat16 ehi = __float2bfloat16(e);
                __nv_bfloat16 elo = __float2bfloat16(e - __bfloat162float(ehi));
                xr[h] = ehi;
                xr[2048 + h] = ehi;
                xr[4096 + h] = elo;
            }
        }
    } else if (t > 0) {
        const int b = bid - 64;
        const int tp = t - 1;
        const float* lg = &g_logits[(long)b * VV];

        float mx = -1e30f;
        for (int v = tid; v < VV; v += 256) mx = fmaxf(mx, lg[v]);
        s_red[tid] = mx; __syncthreads();
        for (int s = 128; s; s >>= 1) {
            if (tid < s) s_red[tid] = fmaxf(s_red[tid], s_red[tid + s]);
            __syncthreads();
        }
        mx = s_red[0];
        __syncthreads();

        float sum = 0.f;
        for (int v = tid; v < VV; v += 256) sum += expf(lg[v] - mx);
        s_red[tid] = sum; __syncthreads();
        for (int s = 128; s; s >>= 1) {
            if (tid < s) s_red[tid] += s_red[tid + s];
            __syncthreads();
        }
        const float lse = mx + logf(s_red[0]);

        float* op = &out_dec[((long)(b * TT + tp)) * VV];
        for (int v = tid; v < VV; v += 256) op[v] = lg[v] - lse;
    }

    if (t == TT) return;                 // tail launch: lsm only (uniform)
    gbar2();

    // ---- Phase C: gi split-K, 96 tiles on blocks 0..95 ----
    if (bid < 96) {
        const int z = bid / 24;
        gemm_body(g_x3, g_wih3, nullptr, g_gipart[z],
                  z * 24, 24, 6 * HH, 6 * HH, 3 * HH,
                  0, (bid % 24) * 128, sptr(smem_raw));
    }
    gbar2();

    // ---- Phase D: GRU over all 128 blocks ----
    for (int idx = bid * 256 + tid; idx < BB * HH; idx += NBLK2 * 256) {
        const int b = idx >> 10, j = idx & 1023;
        const int base = b * 3 * HH;
        float ir = 0, iz = 0, in = 0;
#pragma unroll
        for (int z = 0; z < 4; z++) {
            ir += g_gipart[z][base + j];
            iz += g_gipart[z][base + HH + j];
            in += g_gipart[z][base + 2 * HH + j];
        }
        const float* q0 = &g_qghp[0][b * 4 * HH];
        const float* q1 = &g_qghp[1][b * 4 * HH];
        float hr = q0[HH + j] + q1[HH + j];
        float hz = q0[2 * HH + j] + q1[2 * HH + j];
        float hn = q0[3 * HH + j] + q1[3 * HH + j];
        ir += b_ih[j]; iz += b_ih[HH + j]; in += b_ih[2 * HH + j];
        hr += b_hh[j]; hz += b_hh[HH + j]; hn += b_hh[2 * HH + j];
        float r = 1.f / (1.f + expf(-(ir + hr)));
        float z = 1.f / (1.f + expf(-(iz + hz)));
        float n = tanhf(in + r * hn);
        float ho = g_h[idx];
        float out = (1.f - z) * n + z * ho;
        g_h[idx] = out;
        __nv_bfloat16 hi = __float2bfloat16(out);
        __nv_bfloat16 lo = __float2bfloat16(out - __bfloat162float(hi));
        g_h3[b * 3072 + j] = hi;
        g_h3[b * 3072 + 1024 + j] = hi;
        g_h3[b * 3072 + 2048 + j] = lo;
    }
}

// ---------------------------------------------------------------------------
// Prologue kernels (vectorized x8)
// ---------------------------------------------------------------------------
__global__ void conv_bf16_v8(const float* __restrict__ s,
                             __nv_bfloat16* __restrict__ d)
{
    long i = ((long)blockIdx.x * 256 + threadIdx.x) * 8;
    float4 a = *(const float4*)(s + i);
    float4 b = *(const float4*)(s + i + 4);
    __nv_bfloat162 h[4];
    h[0] = __floats2bfloat162_rn(a.x, a.y);
    h[1] = __floats2bfloat162_rn(a.z, a.w);
    h[2] = __floats2bfloat162_rn(b.x, b.y);
    h[3] = __floats2bfloat162_rn(b.z, b.w);
    *(uint4*)(d + i) = *(uint4*)h;
}

// bf16x3 split x8. isA=1: [hi,hi,lo] (activation); isA=0: [hi,lo,hi] (weight)
__global__ void split3_v8(const float* __restrict__ in,
                          __nv_bfloat16* __restrict__ out, int K, int isA)
{
    const long tid = (long)blockIdx.x * 256 + threadIdx.x;
    const int kv = K >> 3;
    const long r = tid / kv;
    const int k = (int)(tid - r * kv) << 3;
    const float* ip = in + r * K + k;
    float4 a = *(const float4*)ip;
    float4 b = *(const float4*)(ip + 4);
    float v[8] = {a.x, a.y, a.z, a.w, b.x, b.y, b.z, b.w};
    __nv_bfloat16 hi[8], lo[8];
#pragma unroll
    for (int i = 0; i < 8; i++) {
        hi[i] = __float2bfloat16(v[i]);
        lo[i] = __float2bfloat16(v[i] - __bfloat162float(hi[i]));
    }
    long o = r * 3 * K + k;
    *(uint4*)(out + o) = *(uint4*)hi;
    *(uint4*)(out + o + K) = isA ? *(uint4*)hi : *(uint4*)lo;
    *(uint4*)(out + o + 2 * K) = isA ? *(uint4*)lo : *(uint4*)hi;
}

__global__ void copy_h0(const float* __restrict__ h0)
{
    int i = blockIdx.x * 256 + threadIdx.x;
    float v = h0[i];
    g_h[i] = v;
    int r = i >> 10, k = i & 1023;
    __nv_bfloat16 hi = __float2bfloat16(v);
    __nv_bfloat16 lo = __float2bfloat16(v - __bfloat162float(hi));
    g_h3[r * 3072 + k] = hi;
    g_h3[r * 3072 + 1024 + k] = hi;
    g_h3[r * 3072 + 2048 + k] = lo;
    if (i < 2) g_b2[i] = 0;             // barrier state clean each replay
}

__global__ void write_hidden(float* __restrict__ out_hid)
{
    int i = blockIdx.x * 256 + threadIdx.x;
    out_hid[i] = g_h[i];
}

// ---------------------------------------------------------------------------
extern "C" void kernel_launch(void* const* d_in, const int* in_sizes, int n_in,
                              void* d_out, int out_size)
{
    const float* EO     = (const float*)d_in[0];   // [B,S,H]
    const float* h0     = (const float*)d_in[1];   // [B,H]
    const int*   target = (const int*)  d_in[2];   // [B,T]
    const float* emb    = (const float*)d_in[3];   // [V,H]
    const float* Wa     = (const float*)d_in[4];   // [H,H]
    const float* ba     = (const float*)d_in[5];
    const float* Ua     = (const float*)d_in[6];   // [H,H]
    const float* bu     = (const float*)d_in[7];
    const float* Va     = (const float*)d_in[8];   // [1,H]
    const float* bvp    = (const float*)d_in[9];
    const float* W_ih   = (const float*)d_in[10];  // [3H,2H]
    const float* W_hh   = (const float*)d_in[11];  // [3H,H]
    const float* b_ih   = (const float*)d_in[12];
    const float* b_hh   = (const float*)d_in[13];
    const float* W_out  = (const float*)d_in[14];  // [V,H]
    const float* b_out  = (const float*)d_in[15];

    float* out      = (float*)d_out;
    float* out_dec  = out;                          // [B,T,V]
    float* out_hid  = out + (long)BB * TT * VV;     // [1,B,H]
    float* out_attn = out_hid + (long)BB * HH;      // [B,T,S]

    float *p_keysU;
    __nv_bfloat16 *p_wout16, *p_eo3, *p_ua3, *p_wqh3, *p_wih3;
    cudaGetSymbolAddress((void**)&p_keysU,  g_keysU);
    cudaGetSymbolAddress((void**)&p_wout16, g_wout16);
    cudaGetSymbolAddress((void**)&p_eo3,    g_eo3);
    cudaGetSymbolAddress((void**)&p_ua3,    g_ua3);
    cudaGetSymbolAddress((void**)&p_wqh3,   g_wqh3);
    cudaGetSymbolAddress((void**)&p_wih3,   g_wih3);

    cudaFuncSetAttribute(gemm_mma,  cudaFuncAttributeMaxDynamicSharedMemorySize, SMEM_DYN);
    cudaFuncSetAttribute(mega_gemm, cudaFuncAttributeMaxDynamicSharedMemorySize, SMEM_DYN);
    cudaFuncSetAttribute(attn_gi_gru, cudaFuncAttributeMaxDynamicSharedMemorySize, SMEM_DYN);

    // ---- prologue (x8-vectorized) ----
    conv_bf16_v8<<<(VV * HH) / 2048, 256>>>(W_out, p_wout16);
    split3_v8<<<(HH * HH) / 2048, 256>>>(Wa, p_wqh3, HH, 0);
    split3_v8<<<(3 * HH * HH) / 2048, 256>>>(W_hh, p_wqh3 + (long)HH * 3 * HH, HH, 0);
    split3_v8<<<(3 * HH * 2 * HH) / 2048, 256>>>(W_ih, p_wih3, 2 * HH, 0);
    split3_v8<<<(HH * HH) / 2048, 256>>>(Ua, p_ua3, HH, 0);
    split3_v8<<<(BB * SS * HH) / 2048, 256>>>(EO, p_eo3, HH, 1);
    copy_h0<<<BB * HH / 256, 256>>>(h0);

    // keysU = EO @ Ua^T + bu  (bf16x3; one-time)
    gemm_mma<<<dim3(HH / 128, BB * SS / 64, 1), 256, SMEM_DYN>>>(
        p_eo3, p_ua3, bu, p_keysU, 3 * HH / 64, 3 * HH, 3 * HH, HH, 0);

    for (int t = 0; t < TT; t++) {
        // qgh partials + logits_{t-1} (skip at t=0) — one launch (R8-proven)
        mega_gemm<<<QGH2_BLKS + LOGITS_BLKS, 256, SMEM_DYN>>>(
            b_out, (t > 0 ? 1 : 0) | 2);
        // scores -> softmax/ctx/x3 || lsm(t-1) -> gi -> gru — one launch
        attn_gi_gru<<<NBLK2, 256, SMEM_DYN>>>(EO, Va, bvp, ba, emb, target,
                                              b_ih, b_hh, out_attn, out_dec, t);
    }

    // tail: logits_39 + lsm_39
    mega_gemm<<<QGH2_BLKS + LOGITS_BLKS, 256, SMEM_DYN>>>(b_out, 1);
    attn_gi_gru<<<NBLK2, 256, SMEM_DYN>>>(EO, Va, bvp, ba, emb, target,
                                          b_ih, b_hh, out_attn, out_dec, TT);

    write_hidden<<<BB * HH / 256, 256>>>(out_hid);
}

// round 13
// speedup vs baseline: 1.1073x; 1.1073x over previous
#include <cuda_runtime.h>
#include <cuda_bf16.h>
#include <math.h>

#define BB 64
#define SS 64
#define HH 1024
#define TT 40
#define VV 32000

#define LOGITS_BLKS (VV / 128)          // 250
#define QGH4_BLKS   128                 // 32 n-tiles x 4 K-slices
#define SMEM_DYN    73728               // 3 x 24576 (3-stage cp.async pipeline)
#define GI_BLOCKS   96                  // 24 n-tiles x 4 K-slices (co-resident)

// ---------------- scratch (device globals; no allocation allowed) ----------
__device__ float g_keysU[BB * SS * HH];                  // 16.8 MB fp32
__device__ float g_h[BB * HH];
__device__ float g_logits[BB * VV];                      // 8.2 MB
__device__ float g_qghp[4][BB * 4 * HH];                 // qgh split-K partials
__device__ float g_gipart[4][BB * 3 * HH];
__device__ int   g_ctr[2];                               // gi+gru spin barrier
__device__ __nv_bfloat16 g_wout16[(long)VV * HH];        // 65.5 MB
__device__ __nv_bfloat16 g_eo3[(long)BB * SS * 3 * HH];  // [hi,hi,lo] 25 MB
__device__ __nv_bfloat16 g_ua3[(long)HH * 3 * HH];       // [hi,lo,hi] 6 MB
__device__ __nv_bfloat16 g_wqh3[(long)4 * HH * 3 * HH];  // [Wa;Whh] x3, 25 MB
__device__ __nv_bfloat16 g_wih3[(long)3 * HH * 6 * HH];  // W_ih x3, 37.7 MB
__device__ __nv_bfloat16 g_h3[BB * 3 * HH];              // [hi | hi | lo]
__device__ __nv_bfloat16 g_x3[BB * 6 * HH];              // [xhi | xhi | xlo]

// ---------------------------------------------------------------------------
// helpers
// ---------------------------------------------------------------------------
__device__ __forceinline__ float fast_tanh(float x) {
    float y;
    asm("tanh.approx.f32 %0, %1;" : "=f"(y) : "f"(x));
    return y;
}
__device__ __forceinline__ unsigned sptr(const void* p) {
    return (unsigned)__cvta_generic_to_shared(p);
}
__device__ __forceinline__ void cpa16(unsigned dst, const void* src) {
    asm volatile("cp.async.cg.shared.global [%0], [%1], 16;" :: "r"(dst), "l"(src));
}
__device__ __forceinline__ void ldm4(unsigned* r, unsigned addr) {
    asm volatile("ldmatrix.sync.aligned.m8n8.x4.shared.b16 {%0,%1,%2,%3}, [%4];"
                 : "=r"(r[0]), "=r"(r[1]), "=r"(r[2]), "=r"(r[3]) : "r"(addr));
}
__device__ __forceinline__ void mma_bf16(float* d, const unsigned* a,
                                         unsigned b0, unsigned b1) {
    asm volatile(
        "mma.sync.aligned.m16n8k16.row.col.f32.bf16.bf16.f32 "
        "{%0,%1,%2,%3}, {%4,%5,%6,%7}, {%8,%9}, {%0,%1,%2,%3};"
        : "+f"(d[0]), "+f"(d[1]), "+f"(d[2]), "+f"(d[3])
        : "r"(a[0]), "r"(a[1]), "r"(a[2]), "r"(a[3]), "r"(b0), "r"(b1));
}

// ---------------------------------------------------------------------------
// Shared GEMM body (R8-proven, byte-identical): C[64, n0:+128] (+bias) = A@B^T
// cp.async TRIPLE-buffered (wait_group 2), xor-swizzled smem, m16n8k16, 8 warps.
// ---------------------------------------------------------------------------
__device__ __forceinline__ void gemm_body(
    const __nv_bfloat16* __restrict__ A, const __nv_bfloat16* __restrict__ Bw,
    const float* __restrict__ bias, float* __restrict__ C,
    int kcBegin, int kcPer, int lda, int ldb, int ldc,
    int m0, int n0, unsigned sb0)
{
    const unsigned BUF = 24576u;
    const int tid = threadIdx.x;
    const int wid = tid >> 5, lane = tid & 31;
    const int warp_m = wid >> 2;
    const int warp_n = wid & 3;

    float acc[2][4][4];
#pragma unroll
    for (int a = 0; a < 2; a++)
#pragma unroll
        for (int b = 0; b < 4; b++)
#pragma unroll
            for (int c = 0; c < 4; c++) acc[a][b][c] = 0.f;

    auto stage = [&](unsigned sbase, int kc) {
#pragma unroll
        for (int i = 0; i < 6; i++) {
            int idx = tid + i * 256;
            if (idx < 512) {
                int r = idx >> 3, c = idx & 7;
                unsigned dst = sbase + (unsigned)(((r << 3) + (c ^ (r & 7))) << 4);
                cpa16(dst, A + (long)(m0 + r) * lda + kc * 64 + c * 8);
            } else {
                int j = idx - 512;
                int r = j >> 3, c = j & 7;
                unsigned dst = sbase + 8192u + (unsigned)(((r << 3) + (c ^ (r & 7))) << 4);
                cpa16(dst, Bw + (long)(n0 + r) * ldb + kc * 64 + c * 8);
            }
        }
    };

    stage(sb0, kcBegin);
    asm volatile("cp.async.commit_group;");
    if (kcPer > 1) stage(sb0 + BUF, kcBegin + 1);
    asm volatile("cp.async.commit_group;");

    for (int i = 0; i < kcPer; i++) {
        if (i + 2 < kcPer) stage(sb0 + (unsigned)((i + 2) % 3) * BUF, kcBegin + i + 2);
        asm volatile("cp.async.commit_group;");
        asm volatile("cp.async.wait_group 2;");
        __syncthreads();

        const unsigned bA = sb0 + (unsigned)(i % 3) * BUF;
        const unsigned bB = bA + 8192u;

#pragma unroll
        for (int kk = 0; kk < 4; kk++) {
            unsigned afr[2][4], bfr[2][4];
#pragma unroll
            for (int mt = 0; mt < 2; mt++) {
                int r = warp_m * 32 + mt * 16 + (lane & 15);
                int c = 2 * kk + (lane >> 4);
                ldm4(afr[mt], bA + (unsigned)(((r << 3) + (c ^ (r & 7))) << 4));
            }
#pragma unroll
            for (int np = 0; np < 2; np++) {
                int r = warp_n * 32 + np * 16 + ((lane >> 4) << 3) + (lane & 7);
                int c = 2 * kk + ((lane >> 3) & 1);
                ldm4(bfr[np], bB + (unsigned)(((r << 3) + (c ^ (r & 7))) << 4));
            }
#pragma unroll
            for (int mt = 0; mt < 2; mt++)
#pragma unroll
                for (int nt = 0; nt < 4; nt++)
                    mma_bf16(acc[mt][nt], afr[mt],
                             bfr[nt >> 1][(nt & 1) * 2], bfr[nt >> 1][(nt & 1) * 2 + 1]);
        }
        __syncthreads();
    }

#pragma unroll
    for (int mt = 0; mt < 2; mt++) {
        int row = m0 + warp_m * 32 + mt * 16 + (lane >> 2);
#pragma unroll
        for (int nt = 0; nt < 4; nt++) {
            int col = n0 + warp_n * 32 + nt * 8 + ((lane & 3) << 1);
            float* cp = C + (long)row * ldc + col;
            float b0 = 0.f, b1 = 0.f;
            if (bias) { b0 = bias[col]; b1 = bias[col + 1]; }
            float2 v0 = {acc[mt][nt][0] + b0, acc[mt][nt][1] + b1};
            float2 v1 = {acc[mt][nt][2] + b0, acc[mt][nt][3] + b1};
            *(float2*)cp = v0;
            *(float2*)(cp + (long)8 * ldc) = v1;
        }
    }
}

// Generic wrapper (keysU one-time GEMM)
__global__ void gemm_mma(const __nv_bfloat16* __restrict__ A,
                         const __nv_bfloat16* __restrict__ Bw,
                         const float* __restrict__ bias,
                         float* __restrict__ C,
                         int kcPer, int lda, int ldb, int N, long strideZ)
{
    extern __shared__ unsigned char smem_raw[];
    gemm_body(A, Bw, bias, C + (long)blockIdx.z * strideZ,
              blockIdx.z * kcPer, kcPer, lda, ldb, N,
              blockIdx.y * 64, blockIdx.x * 128, sptr(smem_raw));
}

// ---------------------------------------------------------------------------
// MEGA GEMM: qgh split-K4 partials (blocks 0..127, mode&2) + logits (mode&1)
// ONE gemm_body per block (the validated construction). No barrier.
// ---------------------------------------------------------------------------
__global__ void mega_gemm(const float* __restrict__ b_out, int mode)
{
    extern __shared__ unsigned char smem_raw[];
    const int bx = blockIdx.x;
    if (bx < QGH4_BLKS) {
        if (!(mode & 2)) return;
        const int z = bx >> 5;          // K-slice 0..3
        const int n0 = (bx & 31) * 128;
        gemm_body(g_h3, g_wqh3, nullptr, g_qghp[z],
                  z * 12, 12, 3 * HH, 3 * HH, 4 * HH, 0, n0, sptr(smem_raw));
    } else {
        if (!(mode & 1)) return;
        gemm_body(g_h3, g_wout16, b_out, g_logits,
                  0, 16, 3 * HH, HH, VV, 0, (bx - QGH4_BLKS) * 128, sptr(smem_raw));
    }
}

// ---------------------------------------------------------------------------
// gi GEMM + GRU fused (R8-proven shape). grid (24,1,4) = 96 co-resident blocks.
// ---------------------------------------------------------------------------
__global__ void gi_gru(const float* __restrict__ b_ih,
                       const float* __restrict__ b_hh, int t)
{
    extern __shared__ unsigned char smem_raw[];
    const int tid = threadIdx.x;
    const int par = t & 1;
    if (tid == 0 && blockIdx.x == 0 && blockIdx.z == 0)
        g_ctr[1 - par] = 0;             // reset other slot for next step

    gemm_body(g_x3, g_wih3, nullptr, g_gipart[blockIdx.z],
              blockIdx.z * 24, 24, 6 * HH, 6 * HH, 3 * HH,
              0, blockIdx.x * 128, sptr(smem_raw));

    // arrive + spin (all 96 blocks co-resident -> deadlock-free)
    __threadfence();
    __syncthreads();
    if (tid == 0) {
        atomicAdd(&g_ctr[par], 1);
        while (*((volatile int*)&g_ctr[par]) < GI_BLOCKS) __nanosleep(64);
    }
    __syncthreads();
    __threadfence();

    // GRU: each block handles a strided slice of the 64x1024 elements
    const int bid = blockIdx.x + 24 * blockIdx.z;
    for (int idx = bid * 256 + tid; idx < BB * HH; idx += GI_BLOCKS * 256) {
        const int b = idx >> 10, j = idx & 1023;
        const int base = b * 3 * HH;
        float ir = 0, iz = 0, in = 0, hr = 0, hz = 0, hn = 0;
#pragma unroll
        for (int z = 0; z < 4; z++) {
            ir += g_gipart[z][base + j];
            iz += g_gipart[z][base + HH + j];
            in += g_gipart[z][base + 2 * HH + j];
            const float* q = &g_qghp[z][b * 4 * HH];
            hr += q[HH + j];
            hz += q[2 * HH + j];
            hn += q[3 * HH + j];
        }
        ir += b_ih[j]; iz += b_ih[HH + j]; in += b_ih[2 * HH + j];
        hr += b_hh[j]; hz += b_hh[HH + j]; hn += b_hh[2 * HH + j];
        float r = 1.f / (1.f + expf(-(ir + hr)));
        float z = 1.f / (1.f + expf(-(iz + hz)));
        float n = tanhf(in + r * hn);
        float ho = g_h[idx];
        float out = (1.f - z) * n + z * ho;
        g_h[idx] = out;
        __nv_bfloat16 hi = __float2bfloat16(out);
        __nv_bfloat16 lo = __float2bfloat16(out - __bfloat162float(hi));
        g_h3[b * 3072 + j] = hi;
        g_h3[b * 3072 + 1024 + j] = hi;
        g_h3[b * 3072 + 2048 + j] = lo;
    }
}

// ---------------------------------------------------------------------------
// attn (blocks 0..63, mode&1) || ONLINE log-softmax t-1 (64..127, mode&2)
// 512 threads (R8-proven kernel shape).
// ---------------------------------------------------------------------------
__global__ void attn_lsm(const float* __restrict__ EO,
                         const float* __restrict__ Va,
                         const float* __restrict__ bv,
                         const float* __restrict__ ba,
                         const float* __restrict__ emb,
                         const int* __restrict__ target,
                         float* __restrict__ out_attn,
                         float* __restrict__ out_dec,
                         int t, int mode)
{
    __shared__ float qs[HH];
    __shared__ float vs[HH];
    __shared__ float sc[SS];
    __shared__ float w[SS];
    __shared__ float red_m[512];
    __shared__ float red_s[512];
    const int bx = blockIdx.x;
    const int tid = threadIdx.x;

    if (bx < 64) {
        if (!(mode & 1)) return;
        const int b = bx;
        const int warp = tid >> 5, lane = tid & 31;

        for (int i = tid; i < HH; i += 512) {
            qs[i] = g_qghp[0][b * 4 * HH + i] + g_qghp[1][b * 4 * HH + i]
                  + g_qghp[2][b * 4 * HH + i] + g_qghp[3][b * 4 * HH + i] + ba[i];
            vs[i] = Va[i];
        }
        __syncthreads();

        for (int s = warp; s < SS; s += 16) {
            const float* kp = &g_keysU[((long)(b * SS + s)) * HH];
            float sum = 0.f;
            for (int h = lane; h < HH; h += 32)
                sum += fast_tanh(qs[h] + kp[h]) * vs[h];
#pragma unroll
            for (int o = 16; o; o >>= 1) sum += __shfl_xor_sync(~0u, sum, o);
            if (!lane) sc[s] = sum + bv[0];
        }
        __syncthreads();

        if (warp == 0) {
            float v0 = sc[lane], v1 = sc[lane + 32];
            float mx = fmaxf(v0, v1);
#pragma unroll
            for (int o = 16; o; o >>= 1) mx = fmaxf(mx, __shfl_xor_sync(~0u, mx, o));
            float e0 = expf(v0 - mx), e1 = expf(v1 - mx);
            float sm = e0 + e1;
#pragma unroll
            for (int o = 16; o; o >>= 1) sm += __shfl_xor_sync(~0u, sm, o);
            float inv = 1.f / sm;
            w[lane] = e0 * inv;
            w[lane + 32] = e1 * inv;
            out_attn[((long)(b * TT + t)) * SS + lane] = e0 * inv;
            out_attn[((long)(b * TT + t)) * SS + lane + 32] = e1 * inv;
        }
        __syncthreads();

        const int tok = (t == 0) ? 0 : target[b * TT + t - 1];  // SOS_INDEX = 0
        __nv_bfloat16* xr = &g_x3[b * 6 * HH];

        for (int h = tid; h < HH; h += 512) {
            float acc = 0.f;
            const float* ep = &EO[(long)b * SS * HH + h];
#pragma unroll 8
            for (int s = 0; s < SS; s++) acc += w[s] * ep[(long)s * HH];
            __nv_bfloat16 chi = __float2bfloat16(acc);
            __nv_bfloat16 clo = __float2bfloat16(acc - __bfloat162float(chi));
            xr[1024 + h] = chi;
            xr[2048 + 1024 + h] = chi;
            xr[4096 + 1024 + h] = clo;
            float e = emb[(long)tok * HH + h];
            __nv_bfloat16 ehi = __float2bfloat16(e);
            __nv_bfloat16 elo = __float2bfloat16(e - __bfloat162float(ehi));
            xr[h] = ehi;
            xr[2048 + h] = ehi;
            xr[4096 + h] = elo;
        }
    } else {
        if (!(mode & 2)) return;
        const int b = bx - 64;
        const int tp = t - 1;
        const float4* lg4 = (const float4*)&g_logits[(long)b * VV];
        const int n4 = VV / 4;

        // online max+sum in one pass (float4)
        float m = -1e30f, s = 0.f;
        for (int v = tid; v < n4; v += 512) {
            float4 x = lg4[v];
            float cm = fmaxf(fmaxf(x.x, x.y), fmaxf(x.z, x.w));
            float nm = fmaxf(m, cm);
            s = s * expf(m - nm) + expf(x.x - nm) + expf(x.y - nm)
              + expf(x.z - nm) + expf(x.w - nm);
            m = nm;
        }
        red_m[tid] = m; red_s[tid] = s;
        __syncthreads();
        for (int st = 256; st; st >>= 1) {
            if (tid < st) {
                float m1 = red_m[tid], m2 = red_m[tid + st];
                float M = fmaxf(m1, m2);
                red_s[tid] = red_s[tid] * expf(m1 - M)
                           + red_s[tid + st] * expf(m2 - M);
                red_m[tid] = M;
            }
            __syncthreads();
        }
        const float lse = red_m[0] + logf(red_s[0]);
        __syncthreads();

        float4* op4 = (float4*)&out_dec[((long)(b * TT + tp)) * VV];
        for (int v = tid; v < n4; v += 512) {
            float4 x = lg4[v];
            op4[v] = make_float4(x.x - lse, x.y - lse, x.z - lse, x.w - lse);
        }
    }
}

// ---------------------------------------------------------------------------
// Prologue kernels (x8-vectorized, ran correctly in R10/R11)
// ---------------------------------------------------------------------------
__global__ void conv_bf16_v8(const float* __restrict__ s,
                             __nv_bfloat16* __restrict__ d)
{
    long i = ((long)blockIdx.x * 256 + threadIdx.x) * 8;
    float4 a = *(const float4*)(s + i);
    float4 b = *(const float4*)(s + i + 4);
    __nv_bfloat162 h[4];
    h[0] = __floats2bfloat162_rn(a.x, a.y);
    h[1] = __floats2bfloat162_rn(a.z, a.w);
    h[2] = __floats2bfloat162_rn(b.x, b.y);
    h[3] = __floats2bfloat162_rn(b.z, b.w);
    *(uint4*)(d + i) = *(uint4*)h;
}

// bf16x3 split x8. isA=1: [hi,hi,lo] (activation); isA=0: [hi,lo,hi] (weight)
__global__ void split3_v8(const float* __restrict__ in,
                          __nv_bfloat16* __restrict__ out, int K, int isA)
{
    const long tid = (long)blockIdx.x * 256 + threadIdx.x;
    const int kv = K >> 3;
    const long r = tid / kv;
    const int k = (int)(tid - r * kv) << 3;
    const float* ip = in + r * K + k;
    float4 a = *(const float4*)ip;
    float4 b = *(const float4*)(ip + 4);
    float v[8] = {a.x, a.y, a.z, a.w, b.x, b.y, b.z, b.w};
    __nv_bfloat16 hi[8], lo[8];
#pragma unroll
    for (int i = 0; i < 8; i++) {
        hi[i] = __float2bfloat16(v[i]);
        lo[i] = __float2bfloat16(v[i] - __bfloat162float(hi[i]));
    }
    long o = r * 3 * K + k;
    *(uint4*)(out + o) = *(uint4*)hi;
    *(uint4*)(out + o + K) = isA ? *(uint4*)hi : *(uint4*)lo;
    *(uint4*)(out + o + 2 * K) = isA ? *(uint4*)lo : *(uint4*)hi;
}

__global__ void copy_h0(const float* __restrict__ h0)
{
    int i = blockIdx.x * 256 + threadIdx.x;
    float v = h0[i];
    g_h[i] = v;
    int r = i >> 10, k = i & 1023;
    __nv_bfloat16 hi = __float2bfloat16(v);
    __nv_bfloat16 lo = __float2bfloat16(v - __bfloat162float(hi));
    g_h3[r * 3072 + k] = hi;
    g_h3[r * 3072 + 1024 + k] = hi;
    g_h3[r * 3072 + 2048 + k] = lo;
    if (i < 2) g_ctr[i] = 0;            // barrier state clean each replay
}

__global__ void write_hidden(float* __restrict__ out_hid)
{
    int i = blockIdx.x * 256 + threadIdx.x;
    out_hid[i] = g_h[i];
}

// ---------------------------------------------------------------------------
extern "C" void kernel_launch(void* const* d_in, const int* in_sizes, int n_in,
                              void* d_out, int out_size)
{
    const float* EO     = (const float*)d_in[0];   // [B,S,H]
    const float* h0     = (const float*)d_in[1];   // [B,H]
    const int*   target = (const int*)  d_in[2];   // [B,T]
    const float* emb    = (const float*)d_in[3];   // [V,H]
    const float* Wa     = (const float*)d_in[4];   // [H,H]
    const float* ba     = (const float*)d_in[5];
    const float* Ua     = (const float*)d_in[6];   // [H,H]
    const float* bu     = (const float*)d_in[7];
    const float* Va     = (const float*)d_in[8];   // [1,H]
    const float* bvp    = (const float*)d_in[9];
    const float* W_ih   = (const float*)d_in[10];  // [3H,2H]
    const float* W_hh   = (const float*)d_in[11];  // [3H,H]
    const float* b_ih   = (const float*)d_in[12];
    const float* b_hh   = (const float*)d_in[13];
    const float* W_out  = (const float*)d_in[14];  // [V,H]
    const float* b_out  = (const float*)d_in[15];

    float* out      = (float*)d_out;
    float* out_dec  = out;                          // [B,T,V]
    float* out_hid  = out + (long)BB * TT * VV;     // [1,B,H]
    float* out_attn = out_hid + (long)BB * HH;      // [B,T,S]

    float *p_keysU;
    __nv_bfloat16 *p_wout16, *p_eo3, *p_ua3, *p_wqh3, *p_wih3;
    cudaGetSymbolAddress((void**)&p_keysU,  g_keysU);
    cudaGetSymbolAddress((void**)&p_wout16, g_wout16);
    cudaGetSymbolAddress((void**)&p_eo3,    g_eo3);
    cudaGetSymbolAddress((void**)&p_ua3,    g_ua3);
    cudaGetSymbolAddress((void**)&p_wqh3,   g_wqh3);
    cudaGetSymbolAddress((void**)&p_wih3,   g_wih3);

    cudaFuncSetAttribute(gemm_mma,  cudaFuncAttributeMaxDynamicSharedMemorySize, SMEM_DYN);
    cudaFuncSetAttribute(mega_gemm, cudaFuncAttributeMaxDynamicSharedMemorySize, SMEM_DYN);
    cudaFuncSetAttribute(gi_gru,    cudaFuncAttributeMaxDynamicSharedMemorySize, SMEM_DYN);

    // ---- prologue (x8-vectorized) ----
    conv_bf16_v8<<<(VV * HH) / 2048, 256>>>(W_out, p_wout16);
    split3_v8<<<(HH * HH) / 2048, 256>>>(Wa, p_wqh3, HH, 0);
    split3_v8<<<(3 * HH * HH) / 2048, 256>>>(W_hh, p_wqh3 + (long)HH * 3 * HH, HH, 0);
    split3_v8<<<(3 * HH * 2 * HH) / 2048, 256>>>(W_ih, p_wih3, 2 * HH, 0);
    split3_v8<<<(HH * HH) / 2048, 256>>>(Ua, p_ua3, HH, 0);
    split3_v8<<<(BB * SS * HH) / 2048, 256>>>(EO, p_eo3, HH, 1);
    copy_h0<<<BB * HH / 256, 256>>>(h0);

    // keysU = EO @ Ua^T + bu  (bf16x3; one-time)
    gemm_mma<<<dim3(HH / 128, BB * SS / 64, 1), 256, SMEM_DYN>>>(
        p_eo3, p_ua3, bu, p_keysU, 3 * HH / 64, 3 * HH, 3 * HH, HH, 0);

    for (int t = 0; t < TT; t++) {
        // qgh partials (4x12 chunks) + logits_{t-1} (skip at t=0) — one launch
        mega_gemm<<<QGH4_BLKS + LOGITS_BLKS, 256, SMEM_DYN>>>(
            b_out, (t > 0 ? 1 : 0) | 2);
        // attention(t) || online log_softmax(t-1)
        attn_lsm<<<128, 512>>>(EO, Va, bvp, ba, emb, target, out_attn, out_dec,
                               t, 1 | (t > 0 ? 2 : 0));
        // gi partials + GRU, fused with device-side barrier (R8-proven)
        gi_gru<<<dim3(24, 1, 4), 256, SMEM_DYN>>>(b_ih, b_hh, t);
    }

    // tail: logits_39 + lsm_39
    mega_gemm<<<QGH4_BLKS + LOGITS_BLKS, 256, SMEM_DYN>>>(b_out, 1);
    attn_lsm<<<128, 512>>>(EO, Va, bvp, ba, emb, target, out_attn, out_dec,
                           TT, 2);

    write_hidden<<<BB * HH / 256, 256>>>(out_hid);
}

// round 14
// speedup vs baseline: 1.1356x; 1.0256x over previous
#include <cuda_runtime.h>
#include <cuda_bf16.h>
#include <math.h>

#define BB 64
#define SS 64
#define HH 1024
#define TT 40
#define VV 32000

#define LOGITS_BLKS (VV / 128)          // 250
#define QGH4_BLKS   128                 // 32 n-tiles x 4 K-slices
#define SMEM_DYN    73728               // 3 x 24576 (3-stage cp.async pipeline)
#define GI_SPLIT    8                   // gi split-K factor
#define GI_BLOCKS   192                 // 24 n-tiles x 8 K-slices (co-resident)

// ---------------- scratch (device globals; no allocation allowed) ----------
__device__ float g_keysU[BB * SS * HH];                  // 16.8 MB fp32
__device__ float g_h[BB * HH];
__device__ float g_logits[BB * VV];                      // 8.2 MB
__device__ float g_qghp[4][BB * 4 * HH];                 // qgh split-K partials
__device__ float g_gipart[GI_SPLIT][BB * 3 * HH];        // gi split-K partials
__device__ int   g_ctr[2];                               // gi+gru spin barrier
__device__ __nv_bfloat16 g_wout16[(long)VV * HH];        // 65.5 MB
__device__ __nv_bfloat16 g_eo3[(long)BB * SS * 3 * HH];  // [hi,hi,lo] 25 MB
__device__ __nv_bfloat16 g_ua3[(long)HH * 3 * HH];       // [hi,lo,hi] 6 MB
__device__ __nv_bfloat16 g_wqh3[(long)4 * HH * 3 * HH];  // [Wa;Whh] x3, 25 MB
__device__ __nv_bfloat16 g_wih3[(long)3 * HH * 6 * HH];  // W_ih x3, 37.7 MB
__device__ __nv_bfloat16 g_h3[BB * 3 * HH];              // [hi | hi | lo]
__device__ __nv_bfloat16 g_x3[BB * 6 * HH];              // [xhi | xhi | xlo]

// ---------------------------------------------------------------------------
// helpers
// ---------------------------------------------------------------------------
__device__ __forceinline__ float fast_tanh(float x) {
    float y;
    asm("tanh.approx.f32 %0, %1;" : "=f"(y) : "f"(x));
    return y;
}
__device__ __forceinline__ unsigned sptr(const void* p) {
    return (unsigned)__cvta_generic_to_shared(p);
}
__device__ __forceinline__ void cpa16(unsigned dst, const void* src) {
    asm volatile("cp.async.cg.shared.global [%0], [%1], 16;" :: "r"(dst), "l"(src));
}
__device__ __forceinline__ void ldm4(unsigned* r, unsigned addr) {
    asm volatile("ldmatrix.sync.aligned.m8n8.x4.shared.b16 {%0,%1,%2,%3}, [%4];"
                 : "=r"(r[0]), "=r"(r[1]), "=r"(r[2]), "=r"(r[3]) : "r"(addr));
}
__device__ __forceinline__ void mma_bf16(float* d, const unsigned* a,
                                         unsigned b0, unsigned b1) {
    asm volatile(
        "mma.sync.aligned.m16n8k16.row.col.f32.bf16.bf16.f32 "
        "{%0,%1,%2,%3}, {%4,%5,%6,%7}, {%8,%9}, {%0,%1,%2,%3};"
        : "+f"(d[0]), "+f"(d[1]), "+f"(d[2]), "+f"(d[3])
        : "r"(a[0]), "r"(a[1]), "r"(a[2]), "r"(a[3]), "r"(b0), "r"(b1));
}

// ---------------------------------------------------------------------------
// Shared GEMM body (R8-proven, byte-identical): C[64, n0:+128] (+bias) = A@B^T
// cp.async TRIPLE-buffered (wait_group 2), xor-swizzled smem, m16n8k16, 8 warps.
// ---------------------------------------------------------------------------
__device__ __forceinline__ void gemm_body(
    const __nv_bfloat16* __restrict__ A, const __nv_bfloat16* __restrict__ Bw,
    const float* __restrict__ bias, float* __restrict__ C,
    int kcBegin, int kcPer, int lda, int ldb, int ldc,
    int m0, int n0, unsigned sb0)
{
    const unsigned BUF = 24576u;
    const int tid = threadIdx.x;
    const int wid = tid >> 5, lane = tid & 31;
    const int warp_m = wid >> 2;
    const int warp_n = wid & 3;

    float acc[2][4][4];
#pragma unroll
    for (int a = 0; a < 2; a++)
#pragma unroll
        for (int b = 0; b < 4; b++)
#pragma unroll
            for (int c = 0; c < 4; c++) acc[a][b][c] = 0.f;

    auto stage = [&](unsigned sbase, int kc) {
#pragma unroll
        for (int i = 0; i < 6; i++) {
            int idx = tid + i * 256;
            if (idx < 512) {
                int r = idx >> 3, c = idx & 7;
                unsigned dst = sbase + (unsigned)(((r << 3) + (c ^ (r & 7))) << 4);
                cpa16(dst, A + (long)(m0 + r) * lda + kc * 64 + c * 8);
            } else {
                int j = idx - 512;
                int r = j >> 3, c = j & 7;
                unsigned dst = sbase + 8192u + (unsigned)(((r << 3) + (c ^ (r & 7))) << 4);
                cpa16(dst, Bw + (long)(n0 + r) * ldb + kc * 64 + c * 8);
            }
        }
    };

    stage(sb0, kcBegin);
    asm volatile("cp.async.commit_group;");
    if (kcPer > 1) stage(sb0 + BUF, kcBegin + 1);
    asm volatile("cp.async.commit_group;");

    for (int i = 0; i < kcPer; i++) {
        if (i + 2 < kcPer) stage(sb0 + (unsigned)((i + 2) % 3) * BUF, kcBegin + i + 2);
        asm volatile("cp.async.commit_group;");
        asm volatile("cp.async.wait_group 2;");
        __syncthreads();

        const unsigned bA = sb0 + (unsigned)(i % 3) * BUF;
        const unsigned bB = bA + 8192u;

#pragma unroll
        for (int kk = 0; kk < 4; kk++) {
            unsigned afr[2][4], bfr[2][4];
#pragma unroll
            for (int mt = 0; mt < 2; mt++) {
                int r = warp_m * 32 + mt * 16 + (lane & 15);
                int c = 2 * kk + (lane >> 4);
                ldm4(afr[mt], bA + (unsigned)(((r << 3) + (c ^ (r & 7))) << 4));
            }
#pragma unroll
            for (int np = 0; np < 2; np++) {
                int r = warp_n * 32 + np * 16 + ((lane >> 4) << 3) + (lane & 7);
                int c = 2 * kk + ((lane >> 3) & 1);
                ldm4(bfr[np], bB + (unsigned)(((r << 3) + (c ^ (r & 7))) << 4));
            }
#pragma unroll
            for (int mt = 0; mt < 2; mt++)
#pragma unroll
                for (int nt = 0; nt < 4; nt++)
                    mma_bf16(acc[mt][nt], afr[mt],
                             bfr[nt >> 1][(nt & 1) * 2], bfr[nt >> 1][(nt & 1) * 2 + 1]);
        }
        __syncthreads();
    }

#pragma unroll
    for (int mt = 0; mt < 2; mt++) {
        int row = m0 + warp_m * 32 + mt * 16 + (lane >> 2);
#pragma unroll
        for (int nt = 0; nt < 4; nt++) {
            int col = n0 + warp_n * 32 + nt * 8 + ((lane & 3) << 1);
            float* cp = C + (long)row * ldc + col;
            float b0 = 0.f, b1 = 0.f;
            if (bias) { b0 = bias[col]; b1 = bias[col + 1]; }
            float2 v0 = {acc[mt][nt][0] + b0, acc[mt][nt][1] + b1};
            float2 v1 = {acc[mt][nt][2] + b0, acc[mt][nt][3] + b1};
            *(float2*)cp = v0;
            *(float2*)(cp + (long)8 * ldc) = v1;
        }
    }
}

// Generic wrapper (keysU one-time GEMM)
__global__ void gemm_mma(const __nv_bfloat16* __restrict__ A,
                         const __nv_bfloat16* __restrict__ Bw,
                         const float* __restrict__ bias,
                         float* __restrict__ C,
                         int kcPer, int lda, int ldb, int N, long strideZ)
{
    extern __shared__ unsigned char smem_raw[];
    gemm_body(A, Bw, bias, C + (long)blockIdx.z * strideZ,
              blockIdx.z * kcPer, kcPer, lda, ldb, N,
              blockIdx.y * 64, blockIdx.x * 128, sptr(smem_raw));
}

// ---------------------------------------------------------------------------
// MEGA GEMM: qgh split-K4 partials (blocks 0..127, mode&2) + logits (mode&1)
// ONE gemm_body per block (the validated construction). No barrier.
// ---------------------------------------------------------------------------
__global__ void mega_gemm(const float* __restrict__ b_out, int mode)
{
    extern __shared__ unsigned char smem_raw[];
    const int bx = blockIdx.x;
    if (bx < QGH4_BLKS) {
        if (!(mode & 2)) return;
        const int z = bx >> 5;          // K-slice 0..3
        const int n0 = (bx & 31) * 128;
        gemm_body(g_h3, g_wqh3, nullptr, g_qghp[z],
                  z * 12, 12, 3 * HH, 3 * HH, 4 * HH, 0, n0, sptr(smem_raw));
    } else {
        if (!(mode & 1)) return;
        gemm_body(g_h3, g_wout16, b_out, g_logits,
                  0, 16, 3 * HH, HH, VV, 0, (bx - QGH4_BLKS) * 128, sptr(smem_raw));
    }
}

// ---------------------------------------------------------------------------
// gi GEMM + GRU fused. grid (24,1,8) = 192 blocks (<=296 capacity: co-resident).
// 12-chunk chains (halved vs R12). R8-proven construction: one gemm + spin bar.
// ---------------------------------------------------------------------------
__global__ void gi_gru(const float* __restrict__ b_ih,
                       const float* __restrict__ b_hh, int t)
{
    extern __shared__ unsigned char smem_raw[];
    const int tid = threadIdx.x;
    const int par = t & 1;
    if (tid == 0 && blockIdx.x == 0 && blockIdx.z == 0)
        g_ctr[1 - par] = 0;             // reset other slot for next step

    gemm_body(g_x3, g_wih3, nullptr, g_gipart[blockIdx.z],
              blockIdx.z * 12, 12, 6 * HH, 6 * HH, 3 * HH,
              0, blockIdx.x * 128, sptr(smem_raw));

    // arrive + spin (all 192 blocks co-resident -> deadlock-free)
    __threadfence();
    __syncthreads();
    if (tid == 0) {
        atomicAdd(&g_ctr[par], 1);
        while (*((volatile int*)&g_ctr[par]) < GI_BLOCKS) __nanosleep(64);
    }
    __syncthreads();
    __threadfence();

    // GRU: each block handles a strided slice of the 64x1024 elements
    const int bid = blockIdx.x + 24 * blockIdx.z;
    for (int idx = bid * 256 + tid; idx < BB * HH; idx += GI_BLOCKS * 256) {
        const int b = idx >> 10, j = idx & 1023;
        const int base = b * 3 * HH;
        float ir = 0, iz = 0, in = 0;
#pragma unroll
        for (int z = 0; z < GI_SPLIT; z++) {
            ir += g_gipart[z][base + j];
            iz += g_gipart[z][base + HH + j];
            in += g_gipart[z][base + 2 * HH + j];
        }
        float hr = 0, hz = 0, hn = 0;
#pragma unroll
        for (int z = 0; z < 4; z++) {
            const float* q = &g_qghp[z][b * 4 * HH];
            hr += q[HH + j];
            hz += q[2 * HH + j];
            hn += q[3 * HH + j];
        }
        ir += b_ih[j]; iz += b_ih[HH + j]; in += b_ih[2 * HH + j];
        hr += b_hh[j]; hz += b_hh[HH + j]; hn += b_hh[2 * HH + j];
        float r = 1.f / (1.f + expf(-(ir + hr)));
        float z = 1.f / (1.f + expf(-(iz + hz)));
        float n = tanhf(in + r * hn);
        float ho = g_h[idx];
        float out = (1.f - z) * n + z * ho;
        g_h[idx] = out;
        __nv_bfloat16 hi = __float2bfloat16(out);
        __nv_bfloat16 lo = __float2bfloat16(out - __bfloat162float(hi));
        g_h3[b * 3072 + j] = hi;
        g_h3[b * 3072 + 1024 + j] = hi;
        g_h3[b * 3072 + 2048 + j] = lo;
    }
}

// ---------------------------------------------------------------------------
// attn (blocks 0..63, mode&1) || ONLINE log-softmax t-1 (64..127, mode&2)
// 512 threads (R12-proven).
// ---------------------------------------------------------------------------
__global__ void attn_lsm(const float* __restrict__ EO,
                         const float* __restrict__ Va,
                         const float* __restrict__ bv,
                         const float* __restrict__ ba,
                         const float* __restrict__ emb,
                         const int* __restrict__ target,
                         float* __restrict__ out_attn,
                         float* __restrict__ out_dec,
                         int t, int mode)
{
    __shared__ float qs[HH];
    __shared__ float vs[HH];
    __shared__ float sc[SS];
    __shared__ float w[SS];
    __shared__ float red_m[512];
    __shared__ float red_s[512];
    const int bx = blockIdx.x;
    const int tid = threadIdx.x;

    if (bx < 64) {
        if (!(mode & 1)) return;
        const int b = bx;
        const int warp = tid >> 5, lane = tid & 31;

        for (int i = tid; i < HH; i += 512) {
            qs[i] = g_qghp[0][b * 4 * HH + i] + g_qghp[1][b * 4 * HH + i]
                  + g_qghp[2][b * 4 * HH + i] + g_qghp[3][b * 4 * HH + i] + ba[i];
            vs[i] = Va[i];
        }
        __syncthreads();

        for (int s = warp; s < SS; s += 16) {
            const float* kp = &g_keysU[((long)(b * SS + s)) * HH];
            float sum = 0.f;
            for (int h = lane; h < HH; h += 32)
                sum += fast_tanh(qs[h] + kp[h]) * vs[h];
#pragma unroll
            for (int o = 16; o; o >>= 1) sum += __shfl_xor_sync(~0u, sum, o);
            if (!lane) sc[s] = sum + bv[0];
        }
        __syncthreads();

        if (warp == 0) {
            float v0 = sc[lane], v1 = sc[lane + 32];
            float mx = fmaxf(v0, v1);
#pragma unroll
            for (int o = 16; o; o >>= 1) mx = fmaxf(mx, __shfl_xor_sync(~0u, mx, o));
            float e0 = expf(v0 - mx), e1 = expf(v1 - mx);
            float sm = e0 + e1;
#pragma unroll
            for (int o = 16; o; o >>= 1) sm += __shfl_xor_sync(~0u, sm, o);
            float inv = 1.f / sm;
            w[lane] = e0 * inv;
            w[lane + 32] = e1 * inv;
            out_attn[((long)(b * TT + t)) * SS + lane] = e0 * inv;
            out_attn[((long)(b * TT + t)) * SS + lane + 32] = e1 * inv;
        }
        __syncthreads();

        const int tok = (t == 0) ? 0 : target[b * TT + t - 1];  // SOS_INDEX = 0
        __nv_bfloat16* xr = &g_x3[b * 6 * HH];

        for (int h = tid; h < HH; h += 512) {
            float acc = 0.f;
            const float* ep = &EO[(long)b * SS * HH + h];
#pragma unroll 8
            for (int s = 0; s < SS; s++) acc += w[s] * ep[(long)s * HH];
            __nv_bfloat16 chi = __float2bfloat16(acc);
            __nv_bfloat16 clo = __float2bfloat16(acc - __bfloat162float(chi));
            xr[1024 + h] = chi;
            xr[2048 + 1024 + h] = chi;
            xr[4096 + 1024 + h] = clo;
            float e = emb[(long)tok * HH + h];
            __nv_bfloat16 ehi = __float2bfloat16(e);
            __nv_bfloat16 elo = __float2bfloat16(e - __bfloat162float(ehi));
            xr[h] = ehi;
            xr[2048 + h] = ehi;
            xr[4096 + h] = elo;
        }
    } else {
        if (!(mode & 2)) return;
        const int b = bx - 64;
        const int tp = t - 1;
        const float4* lg4 = (const float4*)&g_logits[(long)b * VV];
        const int n4 = VV / 4;

        // online max+sum in one pass (float4)
        float m = -1e30f, s = 0.f;
        for (int v = tid; v < n4; v += 512) {
            float4 x = lg4[v];
            float cm = fmaxf(fmaxf(x.x, x.y), fmaxf(x.z, x.w));
            float nm = fmaxf(m, cm);
            s = s * expf(m - nm) + expf(x.x - nm) + expf(x.y - nm)
              + expf(x.z - nm) + expf(x.w - nm);
            m = nm;
        }
        red_m[tid] = m; red_s[tid] = s;
        __syncthreads();
        for (int st = 256; st; st >>= 1) {
            if (tid < st) {
                float m1 = red_m[tid], m2 = red_m[tid + st];
                float M = fmaxf(m1, m2);
                red_s[tid] = red_s[tid] * expf(m1 - M)
                           + red_s[tid + st] * expf(m2 - M);
                red_m[tid] = M;
            }
            __syncthreads();
        }
        const float lse = red_m[0] + logf(red_s[0]);
        __syncthreads();

        float4* op4 = (float4*)&out_dec[((long)(b * TT + tp)) * VV];
        for (int v = tid; v < n4; v += 512) {
            float4 x = lg4[v];
            op4[v] = make_float4(x.x - lse, x.y - lse, x.z - lse, x.w - lse);
        }
    }
}

// ---------------------------------------------------------------------------
// Prologue: ALL weight splits fused into one kernel (v8-vectorized).
// v8-job ranges: Wa [0,131072) | Whh [131072,524288) | Wih [524288,1310720)
//                Ua [1310720,1441792)
// ---------------------------------------------------------------------------
__global__ void split3_weights(const float* __restrict__ Wa,
                               const float* __restrict__ Whh,
                               const float* __restrict__ Wih,
                               const float* __restrict__ Ua)
{
    long j = (long)blockIdx.x * 256 + threadIdx.x;
    const float* in;
    __nv_bfloat16* outp;
    int K;
    if (j < 131072)       { in = Wa;  outp = g_wqh3;                       K = 1024; }
    else if (j < 524288)  { in = Whh; outp = g_wqh3 + (long)HH * 3 * HH;   K = 1024; j -= 131072; }
    else if (j < 1310720) { in = Wih; outp = g_wih3;                       K = 2048; j -= 524288; }
    else                  { in = Ua;  outp = g_ua3;                        K = 1024; j -= 1310720; }

    const int kv = K >> 3;
    const long r = j / kv;
    const int k = (int)(j - r * kv) << 3;
    const float* ip = in + r * K + k;
    float4 a = *(const float4*)ip;
    float4 b = *(const float4*)(ip + 4);
    float v[8] = {a.x, a.y, a.z, a.w, b.x, b.y, b.z, b.w};
    __nv_bfloat16 hi[8], lo[8];
#pragma unroll
    for (int i = 0; i < 8; i++) {
        hi[i] = __float2bfloat16(v[i]);
        lo[i] = __float2bfloat16(v[i] - __bfloat162float(hi[i]));
    }
    long o = r * 3 * K + k;
    *(uint4*)(outp + o) = *(uint4*)hi;           // weight layout [hi,lo,hi]
    *(uint4*)(outp + o + K) = *(uint4*)lo;
    *(uint4*)(outp + o + 2 * K) = *(uint4*)hi;
}

__global__ void conv_bf16_v8(const float* __restrict__ s,
                             __nv_bfloat16* __restrict__ d)
{
    long i = ((long)blockIdx.x * 256 + threadIdx.x) * 8;
    float4 a = *(const float4*)(s + i);
    float4 b = *(const float4*)(s + i + 4);
    __nv_bfloat162 h[4];
    h[0] = __floats2bfloat162_rn(a.x, a.y);
    h[1] = __floats2bfloat162_rn(a.z, a.w);
    h[2] = __floats2bfloat162_rn(b.x, b.y);
    h[3] = __floats2bfloat162_rn(b.z, b.w);
    *(uint4*)(d + i) = *(uint4*)h;
}

// EO activation split [hi,hi,lo] (v8)
__global__ void split3_eo_v8(const float* __restrict__ in,
                             __nv_bfloat16* __restrict__ out)
{
    const long tid = (long)blockIdx.x * 256 + threadIdx.x;
    const int kv = HH >> 3;
    const long r = tid / kv;
    const int k = (int)(tid - r * kv) << 3;
    const float* ip = in + r * HH + k;
    float4 a = *(const float4*)ip;
    float4 b = *(const float4*)(ip + 4);
    float v[8] = {a.x, a.y, a.z, a.w, b.x, b.y, b.z, b.w};
    __nv_bfloat16 hi[8], lo[8];
#pragma unroll
    for (int i = 0; i < 8; i++) {
        hi[i] = __float2bfloat16(v[i]);
        lo[i] = __float2bfloat16(v[i] - __bfloat162float(hi[i]));
    }
    long o = r * 3 * HH + k;
    *(uint4*)(out + o) = *(uint4*)hi;
    *(uint4*)(out + o + HH) = *(uint4*)hi;
    *(uint4*)(out + o + 2 * HH) = *(uint4*)lo;
}

__global__ void copy_h0(const float* __restrict__ h0)
{
    int i = blockIdx.x * 256 + threadIdx.x;
    float v = h0[i];
    g_h[i] = v;
    int r = i >> 10, k = i & 1023;
    __nv_bfloat16 hi = __float2bfloat16(v);
    __nv_bfloat16 lo = __float2bfloat16(v - __bfloat162float(hi));
    g_h3[r * 3072 + k] = hi;
    g_h3[r * 3072 + 1024 + k] = hi;
    g_h3[r * 3072 + 2048 + k] = lo;
    if (i < 2) g_ctr[i] = 0;            // barrier state clean each replay
}

__global__ void write_hidden(float* __restrict__ out_hid)
{
    int i = blockIdx.x * 256 + threadIdx.x;
    out_hid[i] = g_h[i];
}

// ---------------------------------------------------------------------------
extern "C" void kernel_launch(void* const* d_in, const int* in_sizes, int n_in,
                              void* d_out, int out_size)
{
    const float* EO     = (const float*)d_in[0];   // [B,S,H]
    const float* h0     = (const float*)d_in[1];   // [B,H]
    const int*   target = (const int*)  d_in[2];   // [B,T]
    const float* emb    = (const float*)d_in[3];   // [V,H]
    const float* Wa     = (const float*)d_in[4];   // [H,H]
    const float* ba     = (const float*)d_in[5];
    const float* Ua     = (const float*)d_in[6];   // [H,H]
    const float* bu     = (const float*)d_in[7];
    const float* Va     = (const float*)d_in[8];   // [1,H]
    const float* bvp    = (const float*)d_in[9];
    const float* W_ih   = (const float*)d_in[10];  // [3H,2H]
    const float* W_hh   = (const float*)d_in[11];  // [3H,H]
    const float* b_ih   = (const float*)d_in[12];
    const float* b_hh   = (const float*)d_in[13];
    const float* W_out  = (const float*)d_in[14];  // [V,H]
    const float* b_out  = (const float*)d_in[15];

    float* out      = (float*)d_out;
    float* out_dec  = out;                          // [B,T,V]
    float* out_hid  = out + (long)BB * TT * VV;     // [1,B,H]
    float* out_attn = out_hid + (long)BB * HH;      // [B,T,S]

    float *p_keysU;
    __nv_bfloat16 *p_wout16, *p_eo3, *p_ua3;
    cudaGetSymbolAddress((void**)&p_keysU,  g_keysU);
    cudaGetSymbolAddress((void**)&p_wout16, g_wout16);
    cudaGetSymbolAddress((void**)&p_eo3,    g_eo3);
    cudaGetSymbolAddress((void**)&p_ua3,    g_ua3);

    cudaFuncSetAttribute(gemm_mma,  cudaFuncAttributeMaxDynamicSharedMemorySize, SMEM_DYN);
    cudaFuncSetAttribute(mega_gemm, cudaFuncAttributeMaxDynamicSharedMemorySize, SMEM_DYN);
    cudaFuncSetAttribute(gi_gru,    cudaFuncAttributeMaxDynamicSharedMemorySize, SMEM_DYN);

    // ---- prologue: 5 launches so the FIRST mega_gemm is launch #6 (ncu -s5) ----
    conv_bf16_v8<<<(VV * HH) / 2048, 256>>>(W_out, p_wout16);              // 1
    split3_weights<<<5632, 256>>>(Wa, W_hh, W_ih, Ua);                     // 2
    split3_eo_v8<<<(BB * SS * HH) / 2048, 256>>>(EO, p_eo3);               // 3
    copy_h0<<<BB * HH / 256, 256>>>(h0);                                   // 4
    gemm_mma<<<dim3(HH / 128, BB * SS / 64, 1), 256, SMEM_DYN>>>(          // 5
        p_eo3, p_ua3, bu, p_keysU, 3 * HH / 64, 3 * HH, 3 * HH, HH, 0);

    for (int t = 0; t < TT; t++) {
        // qgh partials (4x12) + logits_{t-1} (skip at t=0) — one launch
        mega_gemm<<<QGH4_BLKS + LOGITS_BLKS, 256, SMEM_DYN>>>(
            b_out, (t > 0 ? 1 : 0) | 2);
        // attention(t) || online log_softmax(t-1)
        attn_lsm<<<128, 512>>>(EO, Va, bvp, ba, emb, target, out_attn, out_dec,
                               t, 1 | (t > 0 ? 2 : 0));
        // gi partials (8x12) + GRU, fused with device-side barrier
        gi_gru<<<dim3(24, 1, GI_SPLIT), 256, SMEM_DYN>>>(b_ih, b_hh, t);
    }

    // tail: logits_39 + lsm_39
    mega_gemm<<<QGH4_BLKS + LOGITS_BLKS, 256, SMEM_DYN>>>(b_out, 1);
    attn_lsm<<<128, 512>>>(EO, Va, bvp, ba, emb, target, out_attn, out_dec,
                           TT, 2);

    write_hidden<<<BB * HH / 256, 256>>>(out_hid);
}